// round 4
// baseline (speedup 1.0000x reference)
#include <cuda_runtime.h>
#include <math.h>

// Problem constants
#define DMODEL 512
#define DFF    2048
#define NHEAD  8
#define DK     64
#define NBLK   4
#define BATCH  2
#define SEQ    2048
#define MROWS  (BATCH*SEQ)   // 4096

// ---------------------------------------------------------------------------
// Scratch (device globals — no allocations allowed)
// ---------------------------------------------------------------------------
__device__ float g_h [MROWS*DMODEL];
__device__ float g_q [MROWS*DMODEL];
__device__ float g_k [MROWS*DMODEL];
__device__ float g_v [MROWS*DMODEL];
__device__ float g_at[MROWS*DMODEL];
__device__ float g_h1[MROWS*DMODEL];
__device__ float g_ff[MROWS*DFF];
__device__ float g_f2[MROWS*DMODEL];

// ---------------------------------------------------------------------------
// Tiled fp32 GEMM: C[M,N] = A[M,K] @ B[K,N] + bias[N], optional ReLU.
// 64x64 tile, BK=32, 256 threads, 4x4 per-thread microtile.
// M % 64 == 0, N % 64 == 0, K % 32 == 0 (true for all shapes here).
// ---------------------------------------------------------------------------
template<bool RELU>
__global__ void gemm_kernel(const float* __restrict__ A,
                            const float* __restrict__ B,
                            const float* __restrict__ bias,
                            float* __restrict__ C,
                            int M, int N, int K) {
    __shared__ float As[32][65];   // As[k][m]
    __shared__ float Bs[32][65];   // Bs[k][n]

    const int tid = threadIdx.x;
    const int tx = tid & 15;
    const int ty = tid >> 4;
    const int row0 = blockIdx.y * 64 + ty * 4;
    const int col0 = blockIdx.x * 64 + tx * 4;

    float acc[4][4];
    #pragma unroll
    for (int i = 0; i < 4; i++)
        #pragma unroll
        for (int j = 0; j < 4; j++) acc[i][j] = 0.f;

    for (int k0 = 0; k0 < K; k0 += 32) {
        // load A tile (64 rows x 32 k), coalesced along K
        #pragma unroll
        for (int i = tid; i < 64 * 32; i += 256) {
            int m  = i >> 5;
            int kk = i & 31;
            As[kk][m] = A[(size_t)(blockIdx.y * 64 + m) * K + k0 + kk];
        }
        // load B tile (32 k x 64 n), coalesced along N
        #pragma unroll
        for (int i = tid; i < 32 * 64; i += 256) {
            int kk = i >> 6;
            int n  = i & 63;
            Bs[kk][n] = B[(size_t)(k0 + kk) * N + blockIdx.x * 64 + n];
        }
        __syncthreads();

        #pragma unroll
        for (int kk = 0; kk < 32; kk++) {
            float a[4], b[4];
            #pragma unroll
            for (int i = 0; i < 4; i++) a[i] = As[kk][ty * 4 + i];
            #pragma unroll
            for (int j = 0; j < 4; j++) b[j] = Bs[kk][tx * 4 + j];
            #pragma unroll
            for (int i = 0; i < 4; i++)
                #pragma unroll
                for (int j = 0; j < 4; j++)
                    acc[i][j] = fmaf(a[i], b[j], acc[i][j]);
        }
        __syncthreads();
    }

    #pragma unroll
    for (int i = 0; i < 4; i++) {
        #pragma unroll
        for (int j = 0; j < 4; j++) {
            float vv = acc[i][j] + bias[col0 + j];
            if (RELU) vv = fmaxf(vv, 0.f);
            C[(size_t)(row0 + i) * N + col0 + j] = vv;
        }
    }
}

// ---------------------------------------------------------------------------
// Flash-attention-style kernel.
// q,k,v,out: [B, S, D] fp32, head h occupies columns [h*64, h*64+64).
// Block = one (batch, head, 64-query tile). 256 threads, 4x4 microtiles.
// Online softmax in registers; replicates the reference quirk:
//   scores exactly equal to 0 are masked to -1e9 (checked per element).
// ---------------------------------------------------------------------------
__global__ void attn_kernel(const float* __restrict__ q,
                            const float* __restrict__ k,
                            const float* __restrict__ v,
                            float* __restrict__ o) {
    extern __shared__ float sm[];
    float (*Qs)[65] = (float(*)[65])(sm);             // Qs[d][r]  (transposed)
    float (*Ks)[65] = (float(*)[65])(sm + 64 * 65);   // Ks[d][c]  (transposed)
    float (*Vs)[65] = (float(*)[65])(sm + 2 * 64 * 65); // Vs[kk][c]
    float (*Ps)[65] = (float(*)[65])(sm + 3 * 64 * 65); // Ps[r][kk]

    const int S = SEQ, D = DMODEL;
    const int qt = blockIdx.x, hh = blockIdx.y, b = blockIdx.z;
    const int tid = threadIdx.x;
    const int tx = tid & 15;
    const int ty = tid >> 4;
    const float scale = 0.125f;   // 1/sqrt(64)

    const float* qbase = q + ((size_t)b * S + qt * 64) * D + hh * 64;
    #pragma unroll
    for (int i = tid; i < 64 * 64; i += 256) {
        int r = i >> 6, c = i & 63;
        Qs[c][r] = qbase[(size_t)r * D + c] * scale;
    }

    float m[4], l[4], O[4][4];
    #pragma unroll
    for (int i = 0; i < 4; i++) {
        m[i] = -1e30f; l[i] = 0.f;
        #pragma unroll
        for (int j = 0; j < 4; j++) O[i][j] = 0.f;
    }
    __syncthreads();

    for (int kt = 0; kt < S / 64; kt++) {
        const float* kbase = k + ((size_t)b * S + kt * 64) * D + hh * 64;
        const float* vbase = v + ((size_t)b * S + kt * 64) * D + hh * 64;
        #pragma unroll
        for (int i = tid; i < 64 * 64; i += 256) {
            int r = i >> 6, c = i & 63;
            Ks[c][r] = kbase[(size_t)r * D + c];
            Vs[r][c] = vbase[(size_t)r * D + c];
        }
        __syncthreads();

        // scores: s[i][j] = sum_d Qs[d][row] * Ks[d][col]   (Q prescaled)
        float s[4][4];
        #pragma unroll
        for (int i = 0; i < 4; i++)
            #pragma unroll
            for (int j = 0; j < 4; j++) s[i][j] = 0.f;

        #pragma unroll 8
        for (int d = 0; d < 64; d++) {
            float a[4], bb[4];
            #pragma unroll
            for (int i = 0; i < 4; i++) a[i] = Qs[d][ty * 4 + i];
            #pragma unroll
            for (int j = 0; j < 4; j++) bb[j] = Ks[d][tx * 4 + j];
            #pragma unroll
            for (int i = 0; i < 4; i++)
                #pragma unroll
                for (int j = 0; j < 4; j++)
                    s[i][j] = fmaf(a[i], bb[j], s[i][j]);
        }

        // quirk + online softmax. Row r=ty*4+i is held by the 16 lanes that
        // share ty (a contiguous 16-lane group within the warp).
        #pragma unroll
        for (int i = 0; i < 4; i++) {
            float tm = -1e30f;
            #pragma unroll
            for (int j = 0; j < 4; j++) {
                if (s[i][j] == 0.0f) s[i][j] = -1e9f;   // reference quirk
                tm = fmaxf(tm, s[i][j]);
            }
            #pragma unroll
            for (int off = 1; off < 16; off <<= 1)
                tm = fmaxf(tm, __shfl_xor_sync(0xffffffffu, tm, off));
            float newm = fmaxf(m[i], tm);
            float corr = expf(m[i] - newm);
            float psum = 0.f;
            #pragma unroll
            for (int j = 0; j < 4; j++) {
                float p = expf(s[i][j] - newm);
                s[i][j] = p;
                psum += p;
            }
            #pragma unroll
            for (int off = 1; off < 16; off <<= 1)
                psum += __shfl_xor_sync(0xffffffffu, psum, off);
            l[i] = l[i] * corr + psum;
            m[i] = newm;
            #pragma unroll
            for (int j = 0; j < 4; j++) O[i][j] *= corr;
        }

        // stage P to shared (columns of O != columns of P per thread)
        #pragma unroll
        for (int i = 0; i < 4; i++)
            #pragma unroll
            for (int j = 0; j < 4; j++)
                Ps[ty * 4 + i][tx * 4 + j] = s[i][j];
        __syncthreads();

        // O += P @ V
        #pragma unroll 8
        for (int kk = 0; kk < 64; kk++) {
            float a[4], bb[4];
            #pragma unroll
            for (int i = 0; i < 4; i++) a[i] = Ps[ty * 4 + i][kk];
            #pragma unroll
            for (int j = 0; j < 4; j++) bb[j] = Vs[kk][tx * 4 + j];
            #pragma unroll
            for (int i = 0; i < 4; i++)
                #pragma unroll
                for (int j = 0; j < 4; j++)
                    O[i][j] = fmaf(a[i], bb[j], O[i][j]);
        }
        __syncthreads();
    }

    float* obase = o + ((size_t)b * S + qt * 64) * D + hh * 64;
    #pragma unroll
    for (int i = 0; i < 4; i++) {
        float inv = 1.f / l[i];
        #pragma unroll
        for (int j = 0; j < 4; j++)
            obase[(size_t)(ty * 4 + i) * D + tx * 4 + j] = O[i][j] * inv;
    }
}

// ---------------------------------------------------------------------------
// Fused residual-add + LayerNorm over D=512. One block per row, 256 threads.
// out = (x - mean)/sqrt(var + eps) * g + beta,  x = a + r
// ---------------------------------------------------------------------------
__global__ void add_ln_kernel(const float* __restrict__ a,
                              const float* __restrict__ r,
                              const float* __restrict__ g,
                              const float* __restrict__ beta,
                              float* __restrict__ out) {
    const int D = DMODEL;
    const int row = blockIdx.x;
    const int tid = threadIdx.x;   // 256 threads, 2 elems each

    float2 xa = ((const float2*)(a + (size_t)row * D))[tid];
    float2 xr = ((const float2*)(r + (size_t)row * D))[tid];
    float x0 = xa.x + xr.x;
    float x1 = xa.y + xr.y;
    float s  = x0 + x1;
    float s2 = x0 * x0 + x1 * x1;

    #pragma unroll
    for (int off = 16; off; off >>= 1) {
        s  += __shfl_xor_sync(0xffffffffu, s,  off);
        s2 += __shfl_xor_sync(0xffffffffu, s2, off);
    }
    __shared__ float sh_s[8], sh_s2[8];
    int w = tid >> 5, lane = tid & 31;
    if (lane == 0) { sh_s[w] = s; sh_s2[w] = s2; }
    __syncthreads();
    if (w == 0) {
        s  = (lane < 8) ? sh_s[lane]  : 0.f;
        s2 = (lane < 8) ? sh_s2[lane] : 0.f;
        #pragma unroll
        for (int off = 4; off; off >>= 1) {
            s  += __shfl_xor_sync(0xffffffffu, s,  off);
            s2 += __shfl_xor_sync(0xffffffffu, s2, off);
        }
        if (lane == 0) { sh_s[0] = s; sh_s2[0] = s2; }
    }
    __syncthreads();

    float mean = sh_s[0]  * (1.f / (float)D);
    float var  = sh_s2[0] * (1.f / (float)D) - mean * mean;
    float rstd = rsqrtf(var + 1e-5f);

    int c0 = tid * 2;
    float y0 = (x0 - mean) * rstd * g[c0]     + beta[c0];
    float y1 = (x1 - mean) * rstd * g[c0 + 1] + beta[c0 + 1];
    ((float2*)(out + (size_t)row * D))[tid] = make_float2(y0, y1);
}

// ---------------------------------------------------------------------------
// Launch
// ---------------------------------------------------------------------------
extern "C" void kernel_launch(void* const* d_in, const int* in_sizes, int n_in,
                              void* d_out, int out_size) {
    const float* x   = (const float*)d_in[0];
    const float* Wq  = (const float*)d_in[1];
    const float* bq  = (const float*)d_in[2];
    const float* Wk  = (const float*)d_in[3];
    const float* bk  = (const float*)d_in[4];
    const float* Wv  = (const float*)d_in[5];
    const float* bv  = (const float*)d_in[6];
    const float* W1  = (const float*)d_in[7];
    const float* b1  = (const float*)d_in[8];
    const float* W2  = (const float*)d_in[9];
    const float* b2  = (const float*)d_in[10];
    const float* g1  = (const float*)d_in[11];
    const float* be1 = (const float*)d_in[12];
    const float* g2  = (const float*)d_in[13];
    const float* be2 = (const float*)d_in[14];
    float* out = (float*)d_out;

    float *h_, *q_, *k_, *v_, *at_, *h1_, *ff_, *f2_;
    cudaGetSymbolAddress((void**)&h_,  g_h);
    cudaGetSymbolAddress((void**)&q_,  g_q);
    cudaGetSymbolAddress((void**)&k_,  g_k);
    cudaGetSymbolAddress((void**)&v_,  g_v);
    cudaGetSymbolAddress((void**)&at_, g_at);
    cudaGetSymbolAddress((void**)&h1_, g_h1);
    cudaGetSymbolAddress((void**)&ff_, g_ff);
    cudaGetSymbolAddress((void**)&f2_, g_f2);

    const size_t attn_smem = 4 * 64 * 65 * sizeof(float);   // 66560 B
    cudaFuncSetAttribute(attn_kernel,
                         cudaFuncAttributeMaxDynamicSharedMemorySize,
                         (int)attn_smem);

    const int M = MROWS;
    dim3 thr(256);
    dim3 grid_qkv(DMODEL / 64, M / 64);   // (8, 64)
    dim3 grid_ff1(DFF    / 64, M / 64);   // (32, 64)
    dim3 grid_ff2(DMODEL / 64, M / 64);   // (8, 64)
    dim3 grid_att(SEQ / 64, NHEAD, BATCH); // (32, 8, 2)

    for (int l = 0; l < NBLK; l++) {
        const float* hin = (l == 0) ? x : h_;

        gemm_kernel<false><<<grid_qkv, thr>>>(hin, Wq + (size_t)l * DMODEL * DMODEL,
                                              bq + (size_t)l * DMODEL, q_, M, DMODEL, DMODEL);
        gemm_kernel<false><<<grid_qkv, thr>>>(hin, Wk + (size_t)l * DMODEL * DMODEL,
                                              bk + (size_t)l * DMODEL, k_, M, DMODEL, DMODEL);
        gemm_kernel<false><<<grid_qkv, thr>>>(hin, Wv + (size_t)l * DMODEL * DMODEL,
                                              bv + (size_t)l * DMODEL, v_, M, DMODEL, DMODEL);

        attn_kernel<<<grid_att, thr, attn_smem>>>(q_, k_, v_, at_);

        add_ln_kernel<<<M, thr>>>(at_, hin, g1 + (size_t)l * DMODEL,
                                  be1 + (size_t)l * DMODEL, h1_);

        gemm_kernel<true ><<<grid_ff1, thr>>>(h1_, W1 + (size_t)l * DMODEL * DFF,
                                              b1 + (size_t)l * DFF, ff_, M, DFF, DMODEL);
        gemm_kernel<false><<<grid_ff2, thr>>>(ff_, W2 + (size_t)l * DFF * DMODEL,
                                              b2 + (size_t)l * DMODEL, f2_, M, DMODEL, DFF);

        float* hout = (l == NBLK - 1) ? out : h_;
        add_ln_kernel<<<M, thr>>>(f2_, h1_, g2 + (size_t)l * DMODEL,
                                  be2 + (size_t)l * DMODEL, hout);
    }
}

// round 6
// speedup vs baseline: 1.9496x; 1.9496x over previous
#include <cuda_runtime.h>
#include <cuda_bf16.h>
#include <math.h>
#include <stdint.h>

// Problem constants
#define DMODEL 512
#define DFF    2048
#define NHEAD  8
#define DK     64
#define NBLK   4
#define BATCH  2
#define SEQ    2048
#define MROWS  (BATCH*SEQ)   // 4096

// ---------------------------------------------------------------------------
// Scratch (device globals — no allocations allowed)
// ---------------------------------------------------------------------------
__device__ float g_h [MROWS*DMODEL];
__device__ float g_q [MROWS*DMODEL];
__device__ float g_k [MROWS*DMODEL];
__device__ float g_v [MROWS*DMODEL];
__device__ float g_at[MROWS*DMODEL];
__device__ float g_h1[MROWS*DMODEL];
__device__ float g_ff[MROWS*DFF];
__device__ float g_f2[MROWS*DMODEL];

// bf16 hi/lo split buffers
// weights, transposed to [N,K]; per-layer: Wq(256K) Wk Wv W1(1M) W2(1M)
#define WOFF_Q  0
#define WOFF_K  262144
#define WOFF_V  524288
#define WOFF_1  786432
#define WOFF_2  1835008
#define WSTRIDE 2883584
__device__ __align__(16) __nv_bfloat16 g_w_hi[NBLK * WSTRIDE];
__device__ __align__(16) __nv_bfloat16 g_w_lo[NBLK * WSTRIDE];
// activations (max 4096 x 2048)
__device__ __align__(16) __nv_bfloat16 g_a_hi[MROWS * DFF];
__device__ __align__(16) __nv_bfloat16 g_a_lo[MROWS * DFF];

// ---------------------------------------------------------------------------
// PTX helpers (sm_80-era features only: valid on compute_103 virtual arch)
// ---------------------------------------------------------------------------
__device__ __forceinline__ uint32_t smem_to_u32(const void* p) {
    uint32_t a;
    asm("{ .reg .u64 t; cvta.to.shared.u64 t, %1; cvt.u32.u64 %0, t; }"
        : "=r"(a) : "l"(p));
    return a;
}
__device__ __forceinline__ void ldsm_x4(uint32_t* r, uint32_t addr) {
    asm volatile("ldmatrix.sync.aligned.m8n8.x4.shared.b16 {%0,%1,%2,%3}, [%4];"
        : "=r"(r[0]), "=r"(r[1]), "=r"(r[2]), "=r"(r[3]) : "r"(addr));
}
__device__ __forceinline__ void mma_bf16(float* d, const uint32_t* a,
                                         const uint32_t* b) {
    asm volatile(
        "mma.sync.aligned.m16n8k16.row.col.f32.bf16.bf16.f32 "
        "{%0,%1,%2,%3}, {%4,%5,%6,%7}, {%8,%9}, {%0,%1,%2,%3};"
        : "+f"(d[0]), "+f"(d[1]), "+f"(d[2]), "+f"(d[3])
        : "r"(a[0]), "r"(a[1]), "r"(a[2]), "r"(a[3]), "r"(b[0]), "r"(b[1]));
}
#define CP_ASYNC16(dst, src) \
    asm volatile("cp.async.cg.shared.global [%0], [%1], 16;" \
        :: "r"(dst), "l"(src))
#define CP_COMMIT() asm volatile("cp.async.commit_group;" ::: "memory")
#define CP_WAIT(N)  asm volatile("cp.async.wait_group %0;" :: "n"(N) : "memory")

// ---------------------------------------------------------------------------
// Activation split: fp32 -> bf16 hi + bf16 lo (elementwise, float4)
// ---------------------------------------------------------------------------
__global__ void split_kernel(const float* __restrict__ in,
                             __nv_bfloat16* __restrict__ hi,
                             __nv_bfloat16* __restrict__ lo, int n4) {
    int i = blockIdx.x * 256 + threadIdx.x;
    if (i >= n4) return;
    float4 v = ((const float4*)in)[i];
    __nv_bfloat16 h0 = __float2bfloat16(v.x);
    __nv_bfloat16 h1 = __float2bfloat16(v.y);
    __nv_bfloat16 h2 = __float2bfloat16(v.z);
    __nv_bfloat16 h3 = __float2bfloat16(v.w);
    __nv_bfloat16 l0 = __float2bfloat16(v.x - __bfloat162float(h0));
    __nv_bfloat16 l1 = __float2bfloat16(v.y - __bfloat162float(h1));
    __nv_bfloat16 l2 = __float2bfloat16(v.z - __bfloat162float(h2));
    __nv_bfloat16 l3 = __float2bfloat16(v.w - __bfloat162float(h3));
    ((__nv_bfloat162*)hi)[2*i]   = __nv_bfloat162(h0, h1);
    ((__nv_bfloat162*)hi)[2*i+1] = __nv_bfloat162(h2, h3);
    ((__nv_bfloat162*)lo)[2*i]   = __nv_bfloat162(l0, l1);
    ((__nv_bfloat162*)lo)[2*i+1] = __nv_bfloat162(l2, l3);
}

// ---------------------------------------------------------------------------
// Weight transpose + split: W[K,N] fp32 -> Whi/Wlo [N,K] bf16
// block (32,8), grid (N/32, K/32)
// ---------------------------------------------------------------------------
__global__ void wsplit_kernel(const float* __restrict__ W,
                              __nv_bfloat16* __restrict__ Whi,
                              __nv_bfloat16* __restrict__ Wlo,
                              int K, int N) {
    __shared__ float t[32][33];
    int n0 = blockIdx.x * 32, k0 = blockIdx.y * 32;
    int tx = threadIdx.x, ty = threadIdx.y;
    #pragma unroll
    for (int r = 0; r < 32; r += 8)
        t[ty + r][tx] = W[(size_t)(k0 + ty + r) * N + n0 + tx];
    __syncthreads();
    #pragma unroll
    for (int r = 0; r < 32; r += 8) {
        float v = t[tx][ty + r];
        __nv_bfloat16 h = __float2bfloat16(v);
        __nv_bfloat16 l = __float2bfloat16(v - __bfloat162float(h));
        size_t o = (size_t)(n0 + ty + r) * K + k0 + tx;
        Whi[o] = h; Wlo[o] = l;
    }
}

// ---------------------------------------------------------------------------
// HMMA GEMM: C[M,N] = A[M,K] @ B^T (B stored [N,K]) + bias, optional ReLU.
// bf16 split: D = Ahi*Bhi + Ahi*Blo + Alo*Bhi (fp32 accumulate in registers).
// CTA tile 128x128, BK=32, 256 threads (8 warps as 4(M) x 2(N), warp 32x64).
// 2-stage cp.async pipeline. SMEM stage = [Ahi|Alo|Bhi|Blo] 8KB each = 32KB.
// SMEM tiles: 128 rows x 64B, XOR swizzle: chunk16 ^= (row>>1)&3  -> ldmatrix
// conflict-free (8 consecutive rows hit 8 distinct 16B slots per 128B line).
// ---------------------------------------------------------------------------
#define STAGE_BYTES 32768
#define GEMM_SMEM   (2*STAGE_BYTES)

__device__ __forceinline__ void stage_load(
    uint32_t sbase,
    const __nv_bfloat16* __restrict__ Ahi, const __nv_bfloat16* __restrict__ Alo,
    const __nv_bfloat16* __restrict__ Bhi, const __nv_bfloat16* __restrict__ Blo,
    int tileM, int tileN, int K, int k0, int tid) {
    #pragma unroll
    for (int h = 0; h < 2; h++) {
        int idx = tid + h * 256;          // 0..511
        int row = idx >> 2;               // 0..127
        int c   = idx & 3;                // 16B chunk within 64B row
        uint32_t sw = (uint32_t)row * 64 + (uint32_t)((c ^ ((row >> 1) & 3)) << 4);
        size_t gA = (size_t)(tileM + row) * K + k0 + c * 8;
        size_t gB = (size_t)(tileN + row) * K + k0 + c * 8;
        CP_ASYNC16(sbase +         sw, Ahi + gA);
        CP_ASYNC16(sbase +  8192 + sw, Alo + gA);
        CP_ASYNC16(sbase + 16384 + sw, Bhi + gB);
        CP_ASYNC16(sbase + 24576 + sw, Blo + gB);
    }
}

template<bool RELU>
__global__ void __launch_bounds__(256) gemm_hmma(
    const __nv_bfloat16* __restrict__ Ahi, const __nv_bfloat16* __restrict__ Alo,
    const __nv_bfloat16* __restrict__ Bhi, const __nv_bfloat16* __restrict__ Blo,
    const float* __restrict__ bias, float* __restrict__ C,
    int M, int N, int K) {
    extern __shared__ char smem[];
    const uint32_t smem_u = smem_to_u32(smem);
    const int tid  = threadIdx.x;
    const int lane = tid & 31;
    const int wid  = tid >> 5;
    const int warp_m = wid & 3;           // 4 warps along M (32 rows each)
    const int warp_n = wid >> 2;          // 2 warps along N (64 cols each)
    const int tileM = blockIdx.y * 128, tileN = blockIdx.x * 128;

    float acc[2][8][4];
    #pragma unroll
    for (int mt = 0; mt < 2; mt++)
        #pragma unroll
        for (int nt = 0; nt < 8; nt++)
            #pragma unroll
            for (int i = 0; i < 4; i++) acc[mt][nt][i] = 0.f;

    // Precompute per-lane ldmatrix smem offsets (within a stage buffer).
    // A x4: lanes 0-7 rows 0-7 klo | 8-15 rows 8-15 klo | 16-23 rows 0-7 khi | 24-31 rows 8-15 khi
    const int a_r = lane & 15;            // row within m16 tile
    const int a_h = lane >> 4;            // k half (0/1)
    // B x4: lanes 0-7 n0-7 klo | 8-15 n0-7 khi | 16-23 n8-15 klo | 24-31 n8-15 khi
    const int b_r = (lane & 7) + ((lane >> 4) << 3);
    const int b_h = (lane >> 3) & 1;

    const int nIter = K >> 5;             // BK = 32
    stage_load(smem_u, Ahi, Alo, Bhi, Blo, tileM, tileN, K, 0, tid);
    CP_COMMIT();

    for (int it = 0; it < nIter; it++) {
        if (it + 1 < nIter) {
            stage_load(smem_u + ((it + 1) & 1) * STAGE_BYTES,
                       Ahi, Alo, Bhi, Blo, tileM, tileN, K, (it + 1) << 5, tid);
            CP_COMMIT();
            CP_WAIT(1);
        } else {
            CP_WAIT(0);
        }
        __syncthreads();

        const uint32_t sbase = smem_u + (it & 1) * STAGE_BYTES;
        #pragma unroll
        for (int kc = 0; kc < 2; kc++) {      // two k16 steps per BK=32
            uint32_t ah[2][4], al[2][4];
            #pragma unroll
            for (int mt = 0; mt < 2; mt++) {
                int row = warp_m * 32 + mt * 16 + a_r;
                int c16 = kc * 2 + a_h;
                uint32_t off = (uint32_t)row * 64 +
                               (uint32_t)((c16 ^ ((row >> 1) & 3)) << 4);
                ldsm_x4(ah[mt], sbase +        off);
                ldsm_x4(al[mt], sbase + 8192 + off);
            }
            uint32_t bh[4][4], bl[4][4];
            #pragma unroll
            for (int nt2 = 0; nt2 < 4; nt2++) {
                int row = warp_n * 64 + nt2 * 16 + b_r;
                int c16 = kc * 2 + b_h;
                uint32_t off = (uint32_t)row * 64 +
                               (uint32_t)((c16 ^ ((row >> 1) & 3)) << 4);
                ldsm_x4(bh[nt2], sbase + 16384 + off);
                ldsm_x4(bl[nt2], sbase + 24576 + off);
            }
            #pragma unroll
            for (int mt = 0; mt < 2; mt++) {
                #pragma unroll
                for (int nt = 0; nt < 8; nt++) {
                    const uint32_t* Bh = &bh[nt >> 1][(nt & 1) * 2];
                    const uint32_t* Bl = &bl[nt >> 1][(nt & 1) * 2];
                    mma_bf16(acc[mt][nt], ah[mt], Bh);
                    mma_bf16(acc[mt][nt], ah[mt], Bl);
                    mma_bf16(acc[mt][nt], al[mt], Bh);
                }
            }
        }
        __syncthreads();
    }

    // Epilogue: bias (+ ReLU), fp32 stores.
    const int l4 = lane >> 2;
    const int l2 = (lane & 3) * 2;
    #pragma unroll
    for (int mt = 0; mt < 2; mt++) {
        #pragma unroll
        for (int nt = 0; nt < 8; nt++) {
            int row = tileM + warp_m * 32 + mt * 16 + l4;
            int col = tileN + warp_n * 64 + nt * 8 + l2;
            float2 bb = *(const float2*)(bias + col);
            float v0 = acc[mt][nt][0] + bb.x;
            float v1 = acc[mt][nt][1] + bb.y;
            float v2 = acc[mt][nt][2] + bb.x;
            float v3 = acc[mt][nt][3] + bb.y;
            if (RELU) {
                v0 = fmaxf(v0, 0.f); v1 = fmaxf(v1, 0.f);
                v2 = fmaxf(v2, 0.f); v3 = fmaxf(v3, 0.f);
            }
            *(float2*)(C + (size_t)row * N + col)       = make_float2(v0, v1);
            *(float2*)(C + (size_t)(row + 8) * N + col) = make_float2(v2, v3);
        }
    }
}

// ---------------------------------------------------------------------------
// Flash-attention-style kernel (unchanged, SIMT fp32).
// ---------------------------------------------------------------------------
__global__ void attn_kernel(const float* __restrict__ q,
                            const float* __restrict__ k,
                            const float* __restrict__ v,
                            float* __restrict__ o) {
    extern __shared__ float sm[];
    float (*Qs)[65] = (float(*)[65])(sm);
    float (*Ks)[65] = (float(*)[65])(sm + 64 * 65);
    float (*Vs)[65] = (float(*)[65])(sm + 2 * 64 * 65);
    float (*Ps)[65] = (float(*)[65])(sm + 3 * 64 * 65);

    const int S = SEQ, D = DMODEL;
    const int qt = blockIdx.x, hh = blockIdx.y, b = blockIdx.z;
    const int tid = threadIdx.x;
    const int tx = tid & 15;
    const int ty = tid >> 4;
    const float scale = 0.125f;

    const float* qbase = q + ((size_t)b * S + qt * 64) * D + hh * 64;
    #pragma unroll
    for (int i = tid; i < 64 * 64; i += 256) {
        int r = i >> 6, c = i & 63;
        Qs[c][r] = qbase[(size_t)r * D + c] * scale;
    }

    float m[4], l[4], O[4][4];
    #pragma unroll
    for (int i = 0; i < 4; i++) {
        m[i] = -1e30f; l[i] = 0.f;
        #pragma unroll
        for (int j = 0; j < 4; j++) O[i][j] = 0.f;
    }
    __syncthreads();

    for (int kt = 0; kt < S / 64; kt++) {
        const float* kbase = k + ((size_t)b * S + kt * 64) * D + hh * 64;
        const float* vbase = v + ((size_t)b * S + kt * 64) * D + hh * 64;
        #pragma unroll
        for (int i = tid; i < 64 * 64; i += 256) {
            int r = i >> 6, c = i & 63;
            Ks[c][r] = kbase[(size_t)r * D + c];
            Vs[r][c] = vbase[(size_t)r * D + c];
        }
        __syncthreads();

        float s[4][4];
        #pragma unroll
        for (int i = 0; i < 4; i++)
            #pragma unroll
            for (int j = 0; j < 4; j++) s[i][j] = 0.f;

        #pragma unroll 8
        for (int d = 0; d < 64; d++) {
            float a[4], bb[4];
            #pragma unroll
            for (int i = 0; i < 4; i++) a[i] = Qs[d][ty * 4 + i];
            #pragma unroll
            for (int j = 0; j < 4; j++) bb[j] = Ks[d][tx * 4 + j];
            #pragma unroll
            for (int i = 0; i < 4; i++)
                #pragma unroll
                for (int j = 0; j < 4; j++)
                    s[i][j] = fmaf(a[i], bb[j], s[i][j]);
        }

        #pragma unroll
        for (int i = 0; i < 4; i++) {
            float tm = -1e30f;
            #pragma unroll
            for (int j = 0; j < 4; j++) {
                if (s[i][j] == 0.0f) s[i][j] = -1e9f;   // reference quirk
                tm = fmaxf(tm, s[i][j]);
            }
            #pragma unroll
            for (int off = 1; off < 16; off <<= 1)
                tm = fmaxf(tm, __shfl_xor_sync(0xffffffffu, tm, off));
            float newm = fmaxf(m[i], tm);
            float corr = expf(m[i] - newm);
            float psum = 0.f;
            #pragma unroll
            for (int j = 0; j < 4; j++) {
                float p = expf(s[i][j] - newm);
                s[i][j] = p;
                psum += p;
            }
            #pragma unroll
            for (int off = 1; off < 16; off <<= 1)
                psum += __shfl_xor_sync(0xffffffffu, psum, off);
            l[i] = l[i] * corr + psum;
            m[i] = newm;
            #pragma unroll
            for (int j = 0; j < 4; j++) O[i][j] *= corr;
        }

        #pragma unroll
        for (int i = 0; i < 4; i++)
            #pragma unroll
            for (int j = 0; j < 4; j++)
                Ps[ty * 4 + i][tx * 4 + j] = s[i][j];
        __syncthreads();

        #pragma unroll 8
        for (int kk = 0; kk < 64; kk++) {
            float a[4], bb[4];
            #pragma unroll
            for (int i = 0; i < 4; i++) a[i] = Ps[ty * 4 + i][kk];
            #pragma unroll
            for (int j = 0; j < 4; j++) bb[j] = Vs[kk][tx * 4 + j];
            #pragma unroll
            for (int i = 0; i < 4; i++)
                #pragma unroll
                for (int j = 0; j < 4; j++)
                    O[i][j] = fmaf(a[i], bb[j], O[i][j]);
        }
        __syncthreads();
    }

    float* obase = o + ((size_t)b * S + qt * 64) * D + hh * 64;
    #pragma unroll
    for (int i = 0; i < 4; i++) {
        float inv = 1.f / l[i];
        #pragma unroll
        for (int j = 0; j < 4; j++)
            obase[(size_t)(ty * 4 + i) * D + tx * 4 + j] = O[i][j] * inv;
    }
}

// ---------------------------------------------------------------------------
// Fused residual-add + LayerNorm (unchanged)
// ---------------------------------------------------------------------------
__global__ void add_ln_kernel(const float* __restrict__ a,
                              const float* __restrict__ r,
                              const float* __restrict__ g,
                              const float* __restrict__ beta,
                              float* __restrict__ out) {
    const int D = DMODEL;
    const int row = blockIdx.x;
    const int tid = threadIdx.x;

    float2 xa = ((const float2*)(a + (size_t)row * D))[tid];
    float2 xr = ((const float2*)(r + (size_t)row * D))[tid];
    float x0 = xa.x + xr.x;
    float x1 = xa.y + xr.y;
    float s  = x0 + x1;
    float s2 = x0 * x0 + x1 * x1;

    #pragma unroll
    for (int off = 16; off; off >>= 1) {
        s  += __shfl_xor_sync(0xffffffffu, s,  off);
        s2 += __shfl_xor_sync(0xffffffffu, s2, off);
    }
    __shared__ float sh_s[8], sh_s2[8];
    int w = tid >> 5, lane = tid & 31;
    if (lane == 0) { sh_s[w] = s; sh_s2[w] = s2; }
    __syncthreads();
    if (w == 0) {
        s  = (lane < 8) ? sh_s[lane]  : 0.f;
        s2 = (lane < 8) ? sh_s2[lane] : 0.f;
        #pragma unroll
        for (int off = 4; off; off >>= 1) {
            s  += __shfl_xor_sync(0xffffffffu, s,  off);
            s2 += __shfl_xor_sync(0xffffffffu, s2, off);
        }
        if (lane == 0) { sh_s[0] = s; sh_s2[0] = s2; }
    }
    __syncthreads();

    float mean = sh_s[0]  * (1.f / (float)D);
    float var  = sh_s2[0] * (1.f / (float)D) - mean * mean;
    float rstd = rsqrtf(var + 1e-5f);

    int c0 = tid * 2;
    float y0 = (x0 - mean) * rstd * g[c0]     + beta[c0];
    float y1 = (x1 - mean) * rstd * g[c0 + 1] + beta[c0 + 1];
    ((float2*)(out + (size_t)row * D))[tid] = make_float2(y0, y1);
}

// ---------------------------------------------------------------------------
// Launch
// ---------------------------------------------------------------------------
extern "C" void kernel_launch(void* const* d_in, const int* in_sizes, int n_in,
                              void* d_out, int out_size) {
    const float* x   = (const float*)d_in[0];
    const float* Wq  = (const float*)d_in[1];
    const float* bq  = (const float*)d_in[2];
    const float* Wk  = (const float*)d_in[3];
    const float* bk  = (const float*)d_in[4];
    const float* Wv  = (const float*)d_in[5];
    const float* bv  = (const float*)d_in[6];
    const float* W1  = (const float*)d_in[7];
    const float* b1  = (const float*)d_in[8];
    const float* W2  = (const float*)d_in[9];
    const float* b2  = (const float*)d_in[10];
    const float* g1  = (const float*)d_in[11];
    const float* be1 = (const float*)d_in[12];
    const float* g2  = (const float*)d_in[13];
    const float* be2 = (const float*)d_in[14];
    float* out = (float*)d_out;

    float *h_, *q_, *k_, *v_, *at_, *h1_, *ff_, *f2_;
    cudaGetSymbolAddress((void**)&h_,  g_h);
    cudaGetSymbolAddress((void**)&q_,  g_q);
    cudaGetSymbolAddress((void**)&k_,  g_k);
    cudaGetSymbolAddress((void**)&v_,  g_v);
    cudaGetSymbolAddress((void**)&at_, g_at);
    cudaGetSymbolAddress((void**)&h1_, g_h1);
    cudaGetSymbolAddress((void**)&ff_, g_ff);
    cudaGetSymbolAddress((void**)&f2_, g_f2);
    __nv_bfloat16 *whi, *wlo, *ahi, *alo;
    cudaGetSymbolAddress((void**)&whi, g_w_hi);
    cudaGetSymbolAddress((void**)&wlo, g_w_lo);
    cudaGetSymbolAddress((void**)&ahi, g_a_hi);
    cudaGetSymbolAddress((void**)&alo, g_a_lo);

    const size_t attn_smem = 4 * 64 * 65 * sizeof(float);
    cudaFuncSetAttribute(attn_kernel,
                         cudaFuncAttributeMaxDynamicSharedMemorySize, (int)attn_smem);
    cudaFuncSetAttribute(gemm_hmma<false>,
                         cudaFuncAttributeMaxDynamicSharedMemorySize, GEMM_SMEM);
    cudaFuncSetAttribute(gemm_hmma<true>,
                         cudaFuncAttributeMaxDynamicSharedMemorySize, GEMM_SMEM);

    const int M = MROWS;
    dim3 thr256(256);
    dim3 wthr(32, 8);

    // Pre-split + transpose all weights into bf16 hi/lo [N,K] buffers.
    for (int l = 0; l < NBLK; l++) {
        size_t wb = (size_t)l * WSTRIDE;
        wsplit_kernel<<<dim3(DMODEL/32, DMODEL/32), wthr>>>(
            Wq + (size_t)l*DMODEL*DMODEL, whi + wb + WOFF_Q, wlo + wb + WOFF_Q, DMODEL, DMODEL);
        wsplit_kernel<<<dim3(DMODEL/32, DMODEL/32), wthr>>>(
            Wk + (size_t)l*DMODEL*DMODEL, whi + wb + WOFF_K, wlo + wb + WOFF_K, DMODEL, DMODEL);
        wsplit_kernel<<<dim3(DMODEL/32, DMODEL/32), wthr>>>(
            Wv + (size_t)l*DMODEL*DMODEL, whi + wb + WOFF_V, wlo + wb + WOFF_V, DMODEL, DMODEL);
        wsplit_kernel<<<dim3(DFF/32, DMODEL/32), wthr>>>(
            W1 + (size_t)l*DMODEL*DFF, whi + wb + WOFF_1, wlo + wb + WOFF_1, DMODEL, DFF);
        wsplit_kernel<<<dim3(DMODEL/32, DFF/32), wthr>>>(
            W2 + (size_t)l*DFF*DMODEL, whi + wb + WOFF_2, wlo + wb + WOFF_2, DFF, DMODEL);
    }

    dim3 g_qkv(DMODEL/128, M/128);   // (4, 32)
    dim3 g_ff1(DFF/128,    M/128);   // (16, 32)
    dim3 g_ff2(DMODEL/128, M/128);   // (4, 32)
    dim3 g_att(SEQ/64, NHEAD, BATCH);
    dim3 thr_g(256);

    for (int l = 0; l < NBLK; l++) {
        const float* hin = (l == 0) ? x : h_;
        size_t wb = (size_t)l * WSTRIDE;

        split_kernel<<<(M*DMODEL/4 + 255)/256, thr256>>>(hin, ahi, alo, M*DMODEL/4);

        gemm_hmma<false><<<g_qkv, thr_g, GEMM_SMEM>>>(
            ahi, alo, whi + wb + WOFF_Q, wlo + wb + WOFF_Q,
            bq + (size_t)l*DMODEL, q_, M, DMODEL, DMODEL);
        gemm_hmma<false><<<g_qkv, thr_g, GEMM_SMEM>>>(
            ahi, alo, whi + wb + WOFF_K, wlo + wb + WOFF_K,
            bk + (size_t)l*DMODEL, k_, M, DMODEL, DMODEL);
        gemm_hmma<false><<<g_qkv, thr_g, GEMM_SMEM>>>(
            ahi, alo, whi + wb + WOFF_V, wlo + wb + WOFF_V,
            bv + (size_t)l*DMODEL, v_, M, DMODEL, DMODEL);

        attn_kernel<<<g_att, thr256, attn_smem>>>(q_, k_, v_, at_);

        add_ln_kernel<<<M, thr256>>>(at_, hin, g1 + (size_t)l*DMODEL,
                                     be1 + (size_t)l*DMODEL, h1_);

        split_kernel<<<(M*DMODEL/4 + 255)/256, thr256>>>(h1_, ahi, alo, M*DMODEL/4);
        gemm_hmma<true><<<g_ff1, thr_g, GEMM_SMEM>>>(
            ahi, alo, whi + wb + WOFF_1, wlo + wb + WOFF_1,
            b1 + (size_t)l*DFF, ff_, M, DFF, DMODEL);

        split_kernel<<<(M*DFF/4 + 255)/256, thr256>>>(ff_, ahi, alo, M*DFF/4);
        gemm_hmma<false><<<g_ff2, thr_g, GEMM_SMEM>>>(
            ahi, alo, whi + wb + WOFF_2, wlo + wb + WOFF_2,
            b2 + (size_t)l*DMODEL, f2_, M, DMODEL, DFF);

        float* hout = (l == NBLK - 1) ? out : h_;
        add_ln_kernel<<<M, thr256>>>(f2_, h1_, g2 + (size_t)l*DMODEL,
                                     be2 + (size_t)l*DMODEL, hout);
    }
}

// round 7
// speedup vs baseline: 4.7585x; 2.4407x over previous
#include <cuda_runtime.h>
#include <cuda_bf16.h>
#include <math.h>
#include <stdint.h>

// Problem constants
#define DMODEL 512
#define DFF    2048
#define NHEAD  8
#define DK     64
#define NBLK   4
#define BATCH  2
#define SEQ    2048
#define MROWS  (BATCH*SEQ)   // 4096

// ---------------------------------------------------------------------------
// Scratch (device globals — no allocations allowed)
// ---------------------------------------------------------------------------
__device__ float g_h [MROWS*DMODEL];   // fp32 block output (residual stream)
__device__ float g_at[MROWS*DMODEL];   // attention output fp32
__device__ float g_h1[MROWS*DMODEL];   // post-LN1 fp32 (residual for LN2)
__device__ float g_f2[MROWS*DMODEL];   // FFN2 output fp32

// bf16 hi/lo split weights, transposed to [N,K]
#define WOFF_Q  0
#define WOFF_K  262144
#define WOFF_V  524288
#define WOFF_1  786432
#define WOFF_2  1835008
#define WSTRIDE 2883584
__device__ __align__(16) __nv_bfloat16 g_w_hi[NBLK * WSTRIDE];
__device__ __align__(16) __nv_bfloat16 g_w_lo[NBLK * WSTRIDE];

// bf16 hi/lo activations
__device__ __align__(16) __nv_bfloat16 g_hh [MROWS*DMODEL]; // h (QKV input)
__device__ __align__(16) __nv_bfloat16 g_hl [MROWS*DMODEL];
__device__ __align__(16) __nv_bfloat16 g_qh [MROWS*DMODEL];
__device__ __align__(16) __nv_bfloat16 g_ql [MROWS*DMODEL];
__device__ __align__(16) __nv_bfloat16 g_kh [MROWS*DMODEL];
__device__ __align__(16) __nv_bfloat16 g_kl [MROWS*DMODEL];
__device__ __align__(16) __nv_bfloat16 g_vh [MROWS*DMODEL];
__device__ __align__(16) __nv_bfloat16 g_vl [MROWS*DMODEL];
__device__ __align__(16) __nv_bfloat16 g_h1h[MROWS*DMODEL];
__device__ __align__(16) __nv_bfloat16 g_h1l[MROWS*DMODEL];
__device__ __align__(16) __nv_bfloat16 g_ffh[MROWS*DFF];
__device__ __align__(16) __nv_bfloat16 g_ffl[MROWS*DFF];

// ---------------------------------------------------------------------------
// PTX helpers (sm_80-era features only: valid on compute_103 virtual arch)
// ---------------------------------------------------------------------------
__device__ __forceinline__ uint32_t smem_to_u32(const void* p) {
    uint32_t a;
    asm("{ .reg .u64 t; cvta.to.shared.u64 t, %1; cvt.u32.u64 %0, t; }"
        : "=r"(a) : "l"(p));
    return a;
}
__device__ __forceinline__ void ldsm_x4(uint32_t* r, uint32_t addr) {
    asm volatile("ldmatrix.sync.aligned.m8n8.x4.shared.b16 {%0,%1,%2,%3}, [%4];"
        : "=r"(r[0]), "=r"(r[1]), "=r"(r[2]), "=r"(r[3]) : "r"(addr));
}
__device__ __forceinline__ void ldsm_x4_t(uint32_t* r, uint32_t addr) {
    asm volatile("ldmatrix.sync.aligned.m8n8.x4.trans.shared.b16 {%0,%1,%2,%3}, [%4];"
        : "=r"(r[0]), "=r"(r[1]), "=r"(r[2]), "=r"(r[3]) : "r"(addr));
}
__device__ __forceinline__ void mma_bf16(float* d, const uint32_t* a,
                                         const uint32_t* b) {
    asm volatile(
        "mma.sync.aligned.m16n8k16.row.col.f32.bf16.bf16.f32 "
        "{%0,%1,%2,%3}, {%4,%5,%6,%7}, {%8,%9}, {%0,%1,%2,%3};"
        : "+f"(d[0]), "+f"(d[1]), "+f"(d[2]), "+f"(d[3])
        : "r"(a[0]), "r"(a[1]), "r"(a[2]), "r"(a[3]), "r"(b[0]), "r"(b[1]));
}
#define CP_ASYNC16(dst, src) \
    asm volatile("cp.async.cg.shared.global [%0], [%1], 16;" \
        :: "r"(dst), "l"(src))
#define CP_COMMIT() asm volatile("cp.async.commit_group;" ::: "memory")
#define CP_WAIT(N)  asm volatile("cp.async.wait_group %0;" :: "n"(N) : "memory")

// Pack a float pair into bf16x2 hi + bf16x2 lo (hi/lo split).
__device__ __forceinline__ void split2(float a, float b,
                                       uint32_t& hi, uint32_t& lo) {
    __nv_bfloat162 h = __float22bfloat162_rn(make_float2(a, b));
    float2 hf = __bfloat1622float2(h);
    __nv_bfloat162 l = __float22bfloat162_rn(make_float2(a - hf.x, b - hf.y));
    hi = *(uint32_t*)&h;
    lo = *(uint32_t*)&l;
}

// ---------------------------------------------------------------------------
// Activation split: fp32 -> bf16 hi + bf16 lo (only used for the layer-0 input)
// ---------------------------------------------------------------------------
__global__ void split_kernel(const float* __restrict__ in,
                             __nv_bfloat16* __restrict__ hi,
                             __nv_bfloat16* __restrict__ lo, int n4) {
    int i = blockIdx.x * 256 + threadIdx.x;
    if (i >= n4) return;
    float4 v = ((const float4*)in)[i];
    uint32_t h01, l01, h23, l23;
    split2(v.x, v.y, h01, l01);
    split2(v.z, v.w, h23, l23);
    ((uint32_t*)hi)[2*i]   = h01;
    ((uint32_t*)hi)[2*i+1] = h23;
    ((uint32_t*)lo)[2*i]   = l01;
    ((uint32_t*)lo)[2*i+1] = l23;
}

// ---------------------------------------------------------------------------
// Weight transpose + split: W[K,N] fp32 -> Whi/Wlo [N,K] bf16
// ---------------------------------------------------------------------------
__global__ void wsplit_kernel(const float* __restrict__ W,
                              __nv_bfloat16* __restrict__ Whi,
                              __nv_bfloat16* __restrict__ Wlo,
                              int K, int N) {
    __shared__ float t[32][33];
    int n0 = blockIdx.x * 32, k0 = blockIdx.y * 32;
    int tx = threadIdx.x, ty = threadIdx.y;
    #pragma unroll
    for (int r = 0; r < 32; r += 8)
        t[ty + r][tx] = W[(size_t)(k0 + ty + r) * N + n0 + tx];
    __syncthreads();
    #pragma unroll
    for (int r = 0; r < 32; r += 8) {
        float v = t[tx][ty + r];
        __nv_bfloat16 h = __float2bfloat16(v);
        __nv_bfloat16 l = __float2bfloat16(v - __bfloat162float(h));
        size_t o = (size_t)(n0 + ty + r) * K + k0 + tx;
        Whi[o] = h; Wlo[o] = l;
    }
}

// ---------------------------------------------------------------------------
// HMMA GEMM: C = A[M,K] @ B^T (B stored [N,K]) + bias.
// bf16 split: D = Ahi*Bhi + Ahi*Blo + Alo*Bhi.
// MODE 0: fp32 out. MODE 1: bf16 hi/lo out. MODE 2: ReLU + bf16 hi/lo out.
// CTA tile 128x128, BK=32, 256 threads, 2-stage cp.async.
// ---------------------------------------------------------------------------
#define STAGE_BYTES 32768
#define GEMM_SMEM   (2*STAGE_BYTES)

__device__ __forceinline__ void stage_load(
    uint32_t sbase,
    const __nv_bfloat16* __restrict__ Ahi, const __nv_bfloat16* __restrict__ Alo,
    const __nv_bfloat16* __restrict__ Bhi, const __nv_bfloat16* __restrict__ Blo,
    int tileM, int tileN, int K, int k0, int tid) {
    #pragma unroll
    for (int h = 0; h < 2; h++) {
        int idx = tid + h * 256;
        int row = idx >> 2;
        int c   = idx & 3;
        uint32_t sw = (uint32_t)row * 64 + (uint32_t)((c ^ ((row >> 1) & 3)) << 4);
        size_t gA = (size_t)(tileM + row) * K + k0 + c * 8;
        size_t gB = (size_t)(tileN + row) * K + k0 + c * 8;
        CP_ASYNC16(sbase +         sw, Ahi + gA);
        CP_ASYNC16(sbase +  8192 + sw, Alo + gA);
        CP_ASYNC16(sbase + 16384 + sw, Bhi + gB);
        CP_ASYNC16(sbase + 24576 + sw, Blo + gB);
    }
}

template<int MODE>
__global__ void __launch_bounds__(256) gemm_hmma(
    const __nv_bfloat16* __restrict__ Ahi, const __nv_bfloat16* __restrict__ Alo,
    const __nv_bfloat16* __restrict__ Bhi, const __nv_bfloat16* __restrict__ Blo,
    const float* __restrict__ bias,
    float* __restrict__ C,
    __nv_bfloat16* __restrict__ Chi, __nv_bfloat16* __restrict__ Clo,
    int M, int N, int K) {
    extern __shared__ char smem[];
    const uint32_t smem_u = smem_to_u32(smem);
    const int tid  = threadIdx.x;
    const int lane = tid & 31;
    const int wid  = tid >> 5;
    const int warp_m = wid & 3;
    const int warp_n = wid >> 2;
    const int tileM = blockIdx.y * 128, tileN = blockIdx.x * 128;

    float acc[2][8][4];
    #pragma unroll
    for (int mt = 0; mt < 2; mt++)
        #pragma unroll
        for (int nt = 0; nt < 8; nt++)
            #pragma unroll
            for (int i = 0; i < 4; i++) acc[mt][nt][i] = 0.f;

    const int a_r = lane & 15;
    const int a_h = lane >> 4;
    const int b_r = (lane & 7) + ((lane >> 4) << 3);
    const int b_h = (lane >> 3) & 1;

    const int nIter = K >> 5;
    stage_load(smem_u, Ahi, Alo, Bhi, Blo, tileM, tileN, K, 0, tid);
    CP_COMMIT();

    for (int it = 0; it < nIter; it++) {
        if (it + 1 < nIter) {
            stage_load(smem_u + ((it + 1) & 1) * STAGE_BYTES,
                       Ahi, Alo, Bhi, Blo, tileM, tileN, K, (it + 1) << 5, tid);
            CP_COMMIT();
            CP_WAIT(1);
        } else {
            CP_WAIT(0);
        }
        __syncthreads();

        const uint32_t sbase = smem_u + (it & 1) * STAGE_BYTES;
        #pragma unroll
        for (int kc = 0; kc < 2; kc++) {
            uint32_t ah[2][4], al[2][4];
            #pragma unroll
            for (int mt = 0; mt < 2; mt++) {
                int row = warp_m * 32 + mt * 16 + a_r;
                int c16 = kc * 2 + a_h;
                uint32_t off = (uint32_t)row * 64 +
                               (uint32_t)((c16 ^ ((row >> 1) & 3)) << 4);
                ldsm_x4(ah[mt], sbase +        off);
                ldsm_x4(al[mt], sbase + 8192 + off);
            }
            uint32_t bh[4][4], bl[4][4];
            #pragma unroll
            for (int nt2 = 0; nt2 < 4; nt2++) {
                int row = warp_n * 64 + nt2 * 16 + b_r;
                int c16 = kc * 2 + b_h;
                uint32_t off = (uint32_t)row * 64 +
                               (uint32_t)((c16 ^ ((row >> 1) & 3)) << 4);
                ldsm_x4(bh[nt2], sbase + 16384 + off);
                ldsm_x4(bl[nt2], sbase + 24576 + off);
            }
            #pragma unroll
            for (int mt = 0; mt < 2; mt++) {
                #pragma unroll
                for (int nt = 0; nt < 8; nt++) {
                    const uint32_t* Bh = &bh[nt >> 1][(nt & 1) * 2];
                    const uint32_t* Bl = &bl[nt >> 1][(nt & 1) * 2];
                    mma_bf16(acc[mt][nt], ah[mt], Bh);
                    mma_bf16(acc[mt][nt], ah[mt], Bl);
                    mma_bf16(acc[mt][nt], al[mt], Bh);
                }
            }
        }
        __syncthreads();
    }

    const int l4 = lane >> 2;
    const int l2 = (lane & 3) * 2;
    #pragma unroll
    for (int mt = 0; mt < 2; mt++) {
        #pragma unroll
        for (int nt = 0; nt < 8; nt++) {
            int row = tileM + warp_m * 32 + mt * 16 + l4;
            int col = tileN + warp_n * 64 + nt * 8 + l2;
            float2 bb = *(const float2*)(bias + col);
            float v0 = acc[mt][nt][0] + bb.x;
            float v1 = acc[mt][nt][1] + bb.y;
            float v2 = acc[mt][nt][2] + bb.x;
            float v3 = acc[mt][nt][3] + bb.y;
            if (MODE == 2) {
                v0 = fmaxf(v0, 0.f); v1 = fmaxf(v1, 0.f);
                v2 = fmaxf(v2, 0.f); v3 = fmaxf(v3, 0.f);
            }
            if (MODE == 0) {
                *(float2*)(C + (size_t)row * N + col)       = make_float2(v0, v1);
                *(float2*)(C + (size_t)(row + 8) * N + col) = make_float2(v2, v3);
            } else {
                uint32_t h01, l01, h23, l23;
                split2(v0, v1, h01, l01);
                split2(v2, v3, h23, l23);
                *(uint32_t*)(Chi + (size_t)row * N + col)       = h01;
                *(uint32_t*)(Clo + (size_t)row * N + col)       = l01;
                *(uint32_t*)(Chi + (size_t)(row + 8) * N + col) = h23;
                *(uint32_t*)(Clo + (size_t)(row + 8) * N + col) = l23;
            }
        }
    }
}

// ---------------------------------------------------------------------------
// Flash attention with HMMA, bf16 hi/lo split for both QK^T and PV.
// CTA: 256 threads (8 warps x 16 query rows = 128 queries) per (head, batch).
// KV chunks of 64, double-buffered cp.async.
// SMEM layout (bytes): stage s at s*32768: Kh 0 | Kl 8192 | Vh 16384 | Vl 24576
//                      Qh at 65536, Ql at 81920.  Total 96KB.
// Row layout: 64 bf16 = 128B per row, 8x16B chunks, swizzle c ^= (row & 7).
// ---------------------------------------------------------------------------
#define ATT_SMEM 98304

__device__ __forceinline__ void att_stage_load(
    uint32_t sbase,
    const __nv_bfloat16* __restrict__ kh, const __nv_bfloat16* __restrict__ kl,
    const __nv_bfloat16* __restrict__ vh, const __nv_bfloat16* __restrict__ vl,
    size_t hoff, int key0, int tid) {
    #pragma unroll
    for (int t = 0; t < 2; t++) {
        int idx = tid + t * 256;
        int row = idx >> 3, c = idx & 7;
        uint32_t off = (uint32_t)row * 128 + (uint32_t)((c ^ (row & 7)) << 4);
        size_t g = hoff + (size_t)(key0 + row) * DMODEL + c * 8;
        CP_ASYNC16(sbase +         off, kh + g);
        CP_ASYNC16(sbase +  8192 + off, kl + g);
        CP_ASYNC16(sbase + 16384 + off, vh + g);
        CP_ASYNC16(sbase + 24576 + off, vl + g);
    }
}

__global__ void __launch_bounds__(256) attn_hmma(
    const __nv_bfloat16* __restrict__ qh, const __nv_bfloat16* __restrict__ ql,
    const __nv_bfloat16* __restrict__ kh, const __nv_bfloat16* __restrict__ kl,
    const __nv_bfloat16* __restrict__ vh, const __nv_bfloat16* __restrict__ vl,
    float* __restrict__ o) {
    extern __shared__ char smem[];
    const uint32_t su = smem_to_u32(smem);
    const int tid = threadIdx.x, lane = tid & 31, wid = tid >> 5;
    const int qt = blockIdx.x, hh = blockIdx.y, b = blockIdx.z;
    const size_t hoff = (size_t)b * SEQ * DMODEL + hh * 64;

    // Load Q tile (128 x 64) hi/lo into smem, swizzled.
    for (int i = tid; i < 1024; i += 256) {
        int row = i >> 3, c = i & 7;
        uint32_t off = (uint32_t)row * 128 + (uint32_t)((c ^ (row & 7)) << 4);
        size_t g = hoff + (size_t)(qt * 128 + row) * DMODEL + c * 8;
        *(uint4*)(smem + 65536 + off) = *(const uint4*)(qh + g);
        *(uint4*)(smem + 81920 + off) = *(const uint4*)(ql + g);
    }

    float m0 = -1e30f, m1 = -1e30f, l0 = 0.f, l1 = 0.f;
    float O[8][4];
    #pragma unroll
    for (int j = 0; j < 8; j++)
        #pragma unroll
        for (int i = 0; i < 4; i++) O[j][i] = 0.f;

    __syncthreads();
    att_stage_load(su, kh, kl, vh, vl, hoff, 0, tid);
    CP_COMMIT();

    const int a_r = lane & 15;           // Q A-frag (non-trans)
    const int a_h = lane >> 4;
    const int b_r = (lane & 7) + ((lane >> 4) << 3);   // K B-frag (non-trans)
    const int b_h = (lane >> 3) & 1;
    const int v_r = (lane & 7) + (((lane >> 3) & 1) << 3);  // V B-frag (trans)
    const int v_h = lane >> 4;

    const int NCH = SEQ / 64;
    for (int ch = 0; ch < NCH; ch++) {
        if (ch + 1 < NCH) {
            att_stage_load(su + ((ch + 1) & 1) * 32768,
                           kh, kl, vh, vl, hoff, (ch + 1) * 64, tid);
            CP_COMMIT();
            CP_WAIT(1);
        } else {
            CP_WAIT(0);
        }
        __syncthreads();
        const uint32_t sb = su + (ch & 1) * 32768;

        // ---- S = Q K^T (3-term hi/lo) ----
        float s[8][4];
        #pragma unroll
        for (int j = 0; j < 8; j++)
            #pragma unroll
            for (int i = 0; i < 4; i++) s[j][i] = 0.f;

        #pragma unroll
        for (int ks = 0; ks < 4; ks++) {
            uint32_t qfh[4], qfl[4];
            {
                int row = wid * 16 + a_r;
                int c16 = ks * 2 + a_h;
                uint32_t off = (uint32_t)row * 128 +
                               (uint32_t)((c16 ^ (row & 7)) << 4);
                ldsm_x4(qfh, su + 65536 + off);
                ldsm_x4(qfl, su + 81920 + off);
            }
            #pragma unroll
            for (int j2 = 0; j2 < 4; j2++) {
                int row = j2 * 16 + b_r;
                int c16 = ks * 2 + b_h;
                uint32_t off = (uint32_t)row * 128 +
                               (uint32_t)((c16 ^ (row & 7)) << 4);
                uint32_t kb[4], klb[4];
                ldsm_x4(kb,  sb +        off);
                ldsm_x4(klb, sb + 8192 + off);
                mma_bf16(s[2*j2],   qfh, kb);
                mma_bf16(s[2*j2],   qfh, klb);
                mma_bf16(s[2*j2],   qfl, kb);
                mma_bf16(s[2*j2+1], qfh, kb + 2);
                mma_bf16(s[2*j2+1], qfh, klb + 2);
                mma_bf16(s[2*j2+1], qfl, kb + 2);
            }
        }

        // ---- scale, quirk, online softmax ----
        float mx0 = -1e30f, mx1 = -1e30f;
        #pragma unroll
        for (int j = 0; j < 8; j++) {
            #pragma unroll
            for (int i = 0; i < 4; i++) {
                float v = s[j][i] * 0.125f;
                if (v == 0.f) v = -1e9f;       // reference quirk
                s[j][i] = v;
            }
            mx0 = fmaxf(mx0, fmaxf(s[j][0], s[j][1]));
            mx1 = fmaxf(mx1, fmaxf(s[j][2], s[j][3]));
        }
        mx0 = fmaxf(mx0, __shfl_xor_sync(0xffffffffu, mx0, 1));
        mx0 = fmaxf(mx0, __shfl_xor_sync(0xffffffffu, mx0, 2));
        mx1 = fmaxf(mx1, __shfl_xor_sync(0xffffffffu, mx1, 1));
        mx1 = fmaxf(mx1, __shfl_xor_sync(0xffffffffu, mx1, 2));

        float nm0 = fmaxf(m0, mx0), nm1 = fmaxf(m1, mx1);
        float c0 = __expf(m0 - nm0), c1 = __expf(m1 - nm1);
        float ps0 = 0.f, ps1 = 0.f;
        #pragma unroll
        for (int j = 0; j < 8; j++) {
            s[j][0] = __expf(s[j][0] - nm0);
            s[j][1] = __expf(s[j][1] - nm0);
            s[j][2] = __expf(s[j][2] - nm1);
            s[j][3] = __expf(s[j][3] - nm1);
            ps0 += s[j][0] + s[j][1];
            ps1 += s[j][2] + s[j][3];
        }
        ps0 += __shfl_xor_sync(0xffffffffu, ps0, 1);
        ps0 += __shfl_xor_sync(0xffffffffu, ps0, 2);
        ps1 += __shfl_xor_sync(0xffffffffu, ps1, 1);
        ps1 += __shfl_xor_sync(0xffffffffu, ps1, 2);
        l0 = l0 * c0 + ps0;  m0 = nm0;
        l1 = l1 * c1 + ps1;  m1 = nm1;
        #pragma unroll
        for (int j = 0; j < 8; j++) {
            O[j][0] *= c0; O[j][1] *= c0;
            O[j][2] *= c1; O[j][3] *= c1;
        }

        // ---- O += P V (3-term hi/lo) ----
        #pragma unroll
        for (int t = 0; t < 4; t++) {       // k16 over keys
            uint32_t pah[4], pal[4];
            split2(s[2*t][0],   s[2*t][1],   pah[0], pal[0]);
            split2(s[2*t][2],   s[2*t][3],   pah[1], pal[1]);
            split2(s[2*t+1][0], s[2*t+1][1], pah[2], pal[2]);
            split2(s[2*t+1][2], s[2*t+1][3], pah[3], pal[3]);
            #pragma unroll
            for (int n2 = 0; n2 < 4; n2++) {
                int row = t * 16 + v_r;
                int c16 = n2 * 2 + v_h;
                uint32_t off = (uint32_t)row * 128 +
                               (uint32_t)((c16 ^ (row & 7)) << 4);
                uint32_t vb[4], vlb[4];
                ldsm_x4_t(vb,  sb + 16384 + off);
                ldsm_x4_t(vlb, sb + 24576 + off);
                mma_bf16(O[2*n2],   pah, vb);
                mma_bf16(O[2*n2],   pah, vlb);
                mma_bf16(O[2*n2],   pal, vb);
                mma_bf16(O[2*n2+1], pah, vb + 2);
                mma_bf16(O[2*n2+1], pah, vlb + 2);
                mma_bf16(O[2*n2+1], pal, vb + 2);
            }
        }
        __syncthreads();
    }

    // ---- normalize and store ----
    float i0 = 1.f / l0, i1 = 1.f / l1;
    int r0 = qt * 128 + wid * 16 + (lane >> 2);
    int colb = hh * 64 + (lane & 3) * 2;
    #pragma unroll
    for (int j = 0; j < 8; j++) {
        int col = colb + j * 8;
        *(float2*)(o + ((size_t)b * SEQ + r0) * DMODEL + col) =
            make_float2(O[j][0] * i0, O[j][1] * i0);
        *(float2*)(o + ((size_t)b * SEQ + r0 + 8) * DMODEL + col) =
            make_float2(O[j][2] * i1, O[j][3] * i1);
    }
}

// ---------------------------------------------------------------------------
// Fused residual-add + LayerNorm, emits fp32 + bf16 hi/lo.
// ---------------------------------------------------------------------------
__global__ void add_ln_kernel(const float* __restrict__ a,
                              const float* __restrict__ r,
                              const float* __restrict__ g,
                              const float* __restrict__ beta,
                              float* __restrict__ out,
                              __nv_bfloat16* __restrict__ ohi,
                              __nv_bfloat16* __restrict__ olo) {
    const int D = DMODEL;
    const int row = blockIdx.x;
    const int tid = threadIdx.x;

    float2 xa = ((const float2*)(a + (size_t)row * D))[tid];
    float2 xr = ((const float2*)(r + (size_t)row * D))[tid];
    float x0 = xa.x + xr.x;
    float x1 = xa.y + xr.y;
    float s  = x0 + x1;
    float s2 = x0 * x0 + x1 * x1;

    #pragma unroll
    for (int off = 16; off; off >>= 1) {
        s  += __shfl_xor_sync(0xffffffffu, s,  off);
        s2 += __shfl_xor_sync(0xffffffffu, s2, off);
    }
    __shared__ float sh_s[8], sh_s2[8];
    int w = tid >> 5, lane = tid & 31;
    if (lane == 0) { sh_s[w] = s; sh_s2[w] = s2; }
    __syncthreads();
    if (w == 0) {
        s  = (lane < 8) ? sh_s[lane]  : 0.f;
        s2 = (lane < 8) ? sh_s2[lane] : 0.f;
        #pragma unroll
        for (int off = 4; off; off >>= 1) {
            s  += __shfl_xor_sync(0xffffffffu, s,  off);
            s2 += __shfl_xor_sync(0xffffffffu, s2, off);
        }
        if (lane == 0) { sh_s[0] = s; sh_s2[0] = s2; }
    }
    __syncthreads();

    float mean = sh_s[0]  * (1.f / (float)D);
    float var  = sh_s2[0] * (1.f / (float)D) - mean * mean;
    float rstd = rsqrtf(var + 1e-5f);

    int c0 = tid * 2;
    float y0 = (x0 - mean) * rstd * g[c0]     + beta[c0];
    float y1 = (x1 - mean) * rstd * g[c0 + 1] + beta[c0 + 1];
    ((float2*)(out + (size_t)row * D))[tid] = make_float2(y0, y1);

    uint32_t h01, l01;
    split2(y0, y1, h01, l01);
    ((uint32_t*)(ohi + (size_t)row * D))[tid] = h01;
    ((uint32_t*)(olo + (size_t)row * D))[tid] = l01;
}

// ---------------------------------------------------------------------------
// Launch
// ---------------------------------------------------------------------------
extern "C" void kernel_launch(void* const* d_in, const int* in_sizes, int n_in,
                              void* d_out, int out_size) {
    const float* x   = (const float*)d_in[0];
    const float* Wq  = (const float*)d_in[1];
    const float* bq  = (const float*)d_in[2];
    const float* Wk  = (const float*)d_in[3];
    const float* bk  = (const float*)d_in[4];
    const float* Wv  = (const float*)d_in[5];
    const float* bv  = (const float*)d_in[6];
    const float* W1  = (const float*)d_in[7];
    const float* b1  = (const float*)d_in[8];
    const float* W2  = (const float*)d_in[9];
    const float* b2  = (const float*)d_in[10];
    const float* g1  = (const float*)d_in[11];
    const float* be1 = (const float*)d_in[12];
    const float* g2  = (const float*)d_in[13];
    const float* be2 = (const float*)d_in[14];
    float* out = (float*)d_out;

    float *h_, *at_, *h1_, *f2_;
    cudaGetSymbolAddress((void**)&h_,  g_h);
    cudaGetSymbolAddress((void**)&at_, g_at);
    cudaGetSymbolAddress((void**)&h1_, g_h1);
    cudaGetSymbolAddress((void**)&f2_, g_f2);
    __nv_bfloat16 *whi, *wlo;
    cudaGetSymbolAddress((void**)&whi, g_w_hi);
    cudaGetSymbolAddress((void**)&wlo, g_w_lo);
    __nv_bfloat16 *hh, *hl, *qh, *ql, *kh, *kl, *vh, *vl, *h1h, *h1l, *ffh, *ffl;
    cudaGetSymbolAddress((void**)&hh,  g_hh);
    cudaGetSymbolAddress((void**)&hl,  g_hl);
    cudaGetSymbolAddress((void**)&qh,  g_qh);
    cudaGetSymbolAddress((void**)&ql,  g_ql);
    cudaGetSymbolAddress((void**)&kh,  g_kh);
    cudaGetSymbolAddress((void**)&kl,  g_kl);
    cudaGetSymbolAddress((void**)&vh,  g_vh);
    cudaGetSymbolAddress((void**)&vl,  g_vl);
    cudaGetSymbolAddress((void**)&h1h, g_h1h);
    cudaGetSymbolAddress((void**)&h1l, g_h1l);
    cudaGetSymbolAddress((void**)&ffh, g_ffh);
    cudaGetSymbolAddress((void**)&ffl, g_ffl);

    cudaFuncSetAttribute(gemm_hmma<0>,
                         cudaFuncAttributeMaxDynamicSharedMemorySize, GEMM_SMEM);
    cudaFuncSetAttribute(gemm_hmma<1>,
                         cudaFuncAttributeMaxDynamicSharedMemorySize, GEMM_SMEM);
    cudaFuncSetAttribute(gemm_hmma<2>,
                         cudaFuncAttributeMaxDynamicSharedMemorySize, GEMM_SMEM);
    cudaFuncSetAttribute(attn_hmma,
                         cudaFuncAttributeMaxDynamicSharedMemorySize, ATT_SMEM);

    const int M = MROWS;
    dim3 thr256(256);
    dim3 wthr(32, 8);

    // Pre-split + transpose all weights into bf16 hi/lo [N,K] buffers.
    for (int l = 0; l < NBLK; l++) {
        size_t wb = (size_t)l * WSTRIDE;
        wsplit_kernel<<<dim3(DMODEL/32, DMODEL/32), wthr>>>(
            Wq + (size_t)l*DMODEL*DMODEL, whi + wb + WOFF_Q, wlo + wb + WOFF_Q, DMODEL, DMODEL);
        wsplit_kernel<<<dim3(DMODEL/32, DMODEL/32), wthr>>>(
            Wk + (size_t)l*DMODEL*DMODEL, whi + wb + WOFF_K, wlo + wb + WOFF_K, DMODEL, DMODEL);
        wsplit_kernel<<<dim3(DMODEL/32, DMODEL/32), wthr>>>(
            Wv + (size_t)l*DMODEL*DMODEL, whi + wb + WOFF_V, wlo + wb + WOFF_V, DMODEL, DMODEL);
        wsplit_kernel<<<dim3(DFF/32, DMODEL/32), wthr>>>(
            W1 + (size_t)l*DMODEL*DFF, whi + wb + WOFF_1, wlo + wb + WOFF_1, DMODEL, DFF);
        wsplit_kernel<<<dim3(DMODEL/32, DFF/32), wthr>>>(
            W2 + (size_t)l*DFF*DMODEL, whi + wb + WOFF_2, wlo + wb + WOFF_2, DFF, DMODEL);
    }

    dim3 g_qkv(DMODEL/128, M/128);     // (4, 32)
    dim3 g_ff1(DFF/128,    M/128);     // (16, 32)
    dim3 g_ff2(DMODEL/128, M/128);     // (4, 32)
    dim3 g_att(SEQ/128, NHEAD, BATCH); // (16, 8, 2)

    // Layer-0 input split.
    split_kernel<<<(M*DMODEL/4 + 255)/256, thr256>>>(x, hh, hl, M*DMODEL/4);

    for (int l = 0; l < NBLK; l++) {
        const float* hin = (l == 0) ? x : h_;
        size_t wb = (size_t)l * WSTRIDE;

        gemm_hmma<1><<<g_qkv, thr256, GEMM_SMEM>>>(
            hh, hl, whi + wb + WOFF_Q, wlo + wb + WOFF_Q,
            bq + (size_t)l*DMODEL, nullptr, qh, ql, M, DMODEL, DMODEL);
        gemm_hmma<1><<<g_qkv, thr256, GEMM_SMEM>>>(
            hh, hl, whi + wb + WOFF_K, wlo + wb + WOFF_K,
            bk + (size_t)l*DMODEL, nullptr, kh, kl, M, DMODEL, DMODEL);
        gemm_hmma<1><<<g_qkv, thr256, GEMM_SMEM>>>(
            hh, hl, whi + wb + WOFF_V, wlo + wb + WOFF_V,
            bv + (size_t)l*DMODEL, nullptr, vh, vl, M, DMODEL, DMODEL);

        attn_hmma<<<g_att, thr256, ATT_SMEM>>>(qh, ql, kh, kl, vh, vl, at_);

        add_ln_kernel<<<M, thr256>>>(at_, hin, g1 + (size_t)l*DMODEL,
                                     be1 + (size_t)l*DMODEL, h1_, h1h, h1l);

        gemm_hmma<2><<<g_ff1, thr256, GEMM_SMEM>>>(
            h1h, h1l, whi + wb + WOFF_1, wlo + wb + WOFF_1,
            b1 + (size_t)l*DFF, nullptr, ffh, ffl, M, DFF, DMODEL);

        gemm_hmma<0><<<g_ff2, thr256, GEMM_SMEM>>>(
            ffh, ffl, whi + wb + WOFF_2, wlo + wb + WOFF_2,
            b2 + (size_t)l*DMODEL, f2_, nullptr, nullptr, M, DMODEL, DFF);

        float* hout = (l == NBLK - 1) ? out : h_;
        add_ln_kernel<<<M, thr256>>>(f2_, h1_, g2 + (size_t)l*DMODEL,
                                     be2 + (size_t)l*DMODEL, hout, hh, hl);
    }
}